// round 1
// baseline (speedup 1.0000x reference)
#include <cuda_runtime.h>
#include <cstdint>

#define BM 64
#define BN 64
#define DHEAD 128
#define NTHR 128
#define KS_STRIDE 132
#define VS_STRIDE 136
#define PS_STRIDE 68
#define AS_STRIDE 68
#define NEGV (-9e15f)

__device__ __forceinline__ uint32_t f2tf32(float f) {
    uint32_t r;
    asm("cvt.rna.tf32.f32 %0, %1;" : "=r"(r) : "f"(f));
    return r;
}

__device__ __forceinline__ void mma_tf32(float c[4], const uint32_t a[4],
                                         uint32_t b0, uint32_t b1) {
    asm volatile(
        "mma.sync.aligned.m16n8k8.row.col.f32.tf32.tf32.f32 "
        "{%0,%1,%2,%3}, {%4,%5,%6,%7}, {%8,%9}, {%0,%1,%2,%3};"
        : "+f"(c[0]), "+f"(c[1]), "+f"(c[2]), "+f"(c[3])
        : "r"(a[0]), "r"(a[1]), "r"(a[2]), "r"(a[3]), "r"(b0), "r"(b1));
}

__global__ __launch_bounds__(NTHR, 2)
void attn_tf32_kernel(const float* __restrict__ Qg, const float* __restrict__ Kg,
                      const float* __restrict__ Vg, const int* __restrict__ Adj,
                      float* __restrict__ Out, int Nseq) {
    extern __shared__ uint32_t smem[];
    uint32_t* Ks = smem;                            // [BN][KS_STRIDE] tf32
    uint32_t* Vs = Ks + BN * KS_STRIDE;             // [BN][VS_STRIDE] tf32
    uint32_t* Ps = Vs + BN * VS_STRIDE;             // [BM][PS_STRIDE] tf32
    int*      As = (int*)(Ps + BM * PS_STRIDE);     // [BM][AS_STRIDE] int

    const int tid  = threadIdx.x;
    const int w    = tid >> 5;
    const int lane = tid & 31;
    const int g    = lane >> 2;   // group id (row within 8)
    const int t4   = lane & 3;    // thread in group
    const int bh   = blockIdx.y;
    const int q0   = blockIdx.x * BM;
    const int rl0  = w * 16 + g;  // local row for c0/c1
    const int rl1  = rl0 + 8;     // local row for c2/c3

    const size_t headoff = (size_t)bh * Nseq * DHEAD;
    const float NEG_INF = __int_as_float(0xff800000);

    // ---- Q fragments (register resident, tf32) ----
    uint32_t qa[16][4];
    {
        const float* Qp0 = Qg + headoff + (size_t)(q0 + rl0) * DHEAD;
        const float* Qp1 = Qg + headoff + (size_t)(q0 + rl1) * DHEAD;
        #pragma unroll
        for (int ks = 0; ks < 16; ks++) {
            int c = ks * 8 + t4;
            qa[ks][0] = f2tf32(Qp0[c]);
            qa[ks][1] = f2tf32(Qp1[c]);
            qa[ks][2] = f2tf32(Qp0[c + 4]);
            qa[ks][3] = f2tf32(Qp1[c + 4]);
        }
    }

    float oacc[16][4];
    #pragma unroll
    for (int nd = 0; nd < 16; nd++) {
        oacc[nd][0] = 0.f; oacc[nd][1] = 0.f; oacc[nd][2] = 0.f; oacc[nd][3] = 0.f;
    }
    float m0 = NEG_INF, m1 = NEG_INF, l0 = 0.f, l1 = 0.f;

    const int ntiles = Nseq / BN;
    for (int kt = 0; kt < ntiles; kt++) {
        __syncthreads();   // protect previous iteration's smem reads

        // ---- load K tile (fp32 -> tf32, SW-free padded layout) ----
        {
            const float* src = Kg + headoff + (size_t)kt * BN * DHEAD;
            #pragma unroll
            for (int i = 0; i < 16; i++) {
                int idx = tid + i * NTHR;          // 0..2047
                int row = idx >> 5;
                int c4  = (idx & 31) << 2;
                float4 v = *(const float4*)(src + row * DHEAD + c4);
                uint4 u;
                u.x = f2tf32(v.x); u.y = f2tf32(v.y);
                u.z = f2tf32(v.z); u.w = f2tf32(v.w);
                *(uint4*)(Ks + row * KS_STRIDE + c4) = u;
            }
        }
        // ---- load V tile ----
        {
            const float* src = Vg + headoff + (size_t)kt * BN * DHEAD;
            #pragma unroll
            for (int i = 0; i < 16; i++) {
                int idx = tid + i * NTHR;
                int row = idx >> 5;
                int c4  = (idx & 31) << 2;
                float4 v = *(const float4*)(src + row * DHEAD + c4);
                uint4 u;
                u.x = f2tf32(v.x); u.y = f2tf32(v.y);
                u.z = f2tf32(v.z); u.w = f2tf32(v.w);
                *(uint4*)(Vs + row * VS_STRIDE + c4) = u;
            }
        }
        // ---- load adj tile [BM rows x BN cols] ----
        {
            const int* src = Adj + (size_t)q0 * Nseq + kt * BN;
            #pragma unroll
            for (int i = 0; i < 8; i++) {
                int idx = tid + i * NTHR;          // 0..1023
                int row = idx >> 4;
                int c4  = (idx & 15) << 2;
                int4 v = *(const int4*)(src + row * Nseq + c4);
                *(int4*)(As + row * AS_STRIDE + c4) = v;
            }
        }
        __syncthreads();

        // ---- S = Q K^T (tf32 mma), warp owns rows [w*16, w*16+16) ----
        float sacc[8][4];
        #pragma unroll
        for (int nb = 0; nb < 8; nb++) {
            sacc[nb][0] = 0.f; sacc[nb][1] = 0.f; sacc[nb][2] = 0.f; sacc[nb][3] = 0.f;
        }
        #pragma unroll
        for (int ks = 0; ks < 16; ks++) {
            #pragma unroll
            for (int nb = 0; nb < 8; nb++) {
                const uint32_t* kp = Ks + (nb * 8 + g) * KS_STRIDE + ks * 8 + t4;
                mma_tf32(sacc[nb], qa[ks], kp[0], kp[4]);
            }
        }

        // ---- mask + scale (match ref: e/8 where adj>0 else -9e15) ----
        const int* ar0 = As + rl0 * AS_STRIDE;
        const int* ar1 = As + rl1 * AS_STRIDE;
        #pragma unroll
        for (int nb = 0; nb < 8; nb++) {
            int c = nb * 8 + 2 * t4;
            sacc[nb][0] = (ar0[c]     > 0) ? sacc[nb][0] * 0.125f : NEGV;
            sacc[nb][1] = (ar0[c + 1] > 0) ? sacc[nb][1] * 0.125f : NEGV;
            sacc[nb][2] = (ar1[c]     > 0) ? sacc[nb][2] * 0.125f : NEGV;
            sacc[nb][3] = (ar1[c + 1] > 0) ? sacc[nb][3] * 0.125f : NEGV;
        }

        // ---- online softmax (fp32) ----
        float mx0 = NEG_INF, mx1 = NEG_INF;
        #pragma unroll
        for (int nb = 0; nb < 8; nb++) {
            mx0 = fmaxf(mx0, fmaxf(sacc[nb][0], sacc[nb][1]));
            mx1 = fmaxf(mx1, fmaxf(sacc[nb][2], sacc[nb][3]));
        }
        mx0 = fmaxf(mx0, __shfl_xor_sync(0xffffffffu, mx0, 1));
        mx0 = fmaxf(mx0, __shfl_xor_sync(0xffffffffu, mx0, 2));
        mx1 = fmaxf(mx1, __shfl_xor_sync(0xffffffffu, mx1, 1));
        mx1 = fmaxf(mx1, __shfl_xor_sync(0xffffffffu, mx1, 2));
        float mn0 = fmaxf(m0, mx0), mn1 = fmaxf(m1, mx1);
        float al0 = __expf(m0 - mn0), al1 = __expf(m1 - mn1);
        m0 = mn0; m1 = mn1;

        float ps0 = 0.f, ps1 = 0.f;
        uint32_t* pw0 = Ps + rl0 * PS_STRIDE + 2 * t4;
        uint32_t* pw1 = Ps + rl1 * PS_STRIDE + 2 * t4;
        #pragma unroll
        for (int nb = 0; nb < 8; nb++) {
            float p0 = __expf(sacc[nb][0] - mn0);
            float p1 = __expf(sacc[nb][1] - mn0);
            float p2 = __expf(sacc[nb][2] - mn1);
            float p3 = __expf(sacc[nb][3] - mn1);
            ps0 += p0 + p1;
            ps1 += p2 + p3;
            uint2 u0; u0.x = f2tf32(p0); u0.y = f2tf32(p1);
            *(uint2*)(pw0 + nb * 8) = u0;
            uint2 u1; u1.x = f2tf32(p2); u1.y = f2tf32(p3);
            *(uint2*)(pw1 + nb * 8) = u1;
        }
        ps0 += __shfl_xor_sync(0xffffffffu, ps0, 1);
        ps0 += __shfl_xor_sync(0xffffffffu, ps0, 2);
        ps1 += __shfl_xor_sync(0xffffffffu, ps1, 1);
        ps1 += __shfl_xor_sync(0xffffffffu, ps1, 2);
        l0 = l0 * al0 + ps0;
        l1 = l1 * al1 + ps1;

        // rescale O accumulator
        #pragma unroll
        for (int nd = 0; nd < 16; nd++) {
            oacc[nd][0] *= al0; oacc[nd][1] *= al0;
            oacc[nd][2] *= al1; oacc[nd][3] *= al1;
        }
        __syncwarp();   // P stores visible within the warp (each warp reads only its own rows)

        // ---- O += P V ----
        #pragma unroll
        for (int ks2 = 0; ks2 < 8; ks2++) {
            uint32_t pa[4];
            const uint32_t* pr0 = Ps + rl0 * PS_STRIDE + ks2 * 8 + t4;
            const uint32_t* pr1 = Ps + rl1 * PS_STRIDE + ks2 * 8 + t4;
            pa[0] = pr0[0]; pa[1] = pr1[0]; pa[2] = pr0[4]; pa[3] = pr1[4];
            const uint32_t* vb0 = Vs + (ks2 * 8 + t4) * VS_STRIDE + g;
            const uint32_t* vb1 = vb0 + 4 * VS_STRIDE;
            #pragma unroll
            for (int nd = 0; nd < 16; nd++) {
                mma_tf32(oacc[nd], pa, vb0[nd * 8], vb1[nd * 8]);
            }
        }
    }

    // ---- epilogue: normalize + store (output layout == [B,H,N,d] linear) ----
    float inv0 = 1.0f / l0;
    float inv1 = 1.0f / l1;
    float* o0 = Out + headoff + (size_t)(q0 + rl0) * DHEAD;
    float* o1 = Out + headoff + (size_t)(q0 + rl1) * DHEAD;
    #pragma unroll
    for (int nd = 0; nd < 16; nd++) {
        int c = nd * 8 + 2 * t4;
        float2 a; a.x = oacc[nd][0] * inv0; a.y = oacc[nd][1] * inv0;
        *(float2*)(o0 + c) = a;
        float2 b; b.x = oacc[nd][2] * inv1; b.y = oacc[nd][3] * inv1;
        *(float2*)(o1 + c) = b;
    }
}

extern "C" void kernel_launch(void* const* d_in, const int* in_sizes, int n_in,
                              void* d_out, int out_size) {
    const float* Q   = (const float*)d_in[0];
    const float* K   = (const float*)d_in[1];
    const float* V   = (const float*)d_in[2];
    const int*   adj = (const int*)d_in[3];
    float* out = (float*)d_out;

    const int Nseq = 1024;                       // adj is [1024,1024]
    const int BH   = in_sizes[0] / (Nseq * DHEAD);  // B*H = 64

    const size_t smem_bytes =
        (size_t)(BN * KS_STRIDE + BN * VS_STRIDE + BM * PS_STRIDE + BM * AS_STRIDE) * 4;

    cudaFuncSetAttribute(attn_tf32_kernel,
                         cudaFuncAttributeMaxDynamicSharedMemorySize,
                         (int)smem_bytes);

    dim3 grid(Nseq / BM, BH);
    attn_tf32_kernel<<<grid, NTHR, smem_bytes>>>(Q, K, V, adj, out, Nseq);
}

// round 3
// speedup vs baseline: 1.0938x; 1.0938x over previous
#include <cuda_runtime.h>
#include <cstdint>

#define NSEQ   1024
#define DHEAD  128
#define BM     64
#define BN     64
#define NTHR   128

// ---- smem layout (bytes) ----
#define KF_WORDS 132                   // words per K fragment (528 B; 132 mod 32 = 4 -> conflict-free)
#define K_OFF    0
#define K_BYTES  (64 * KF_WORDS * 4)   // 64 frags (nb 0..7, kp 0..7) = 33792
#define V_STRIDE 136                   // words per V row
#define V_OFF    K_BYTES
#define V_BYTES  (BN * V_STRIDE * 4)   // 34816
#define SMEM_TOTAL (K_BYTES + V_BYTES) // 68608

__device__ uint32_t g_maskbits[NSEQ * (NSEQ / 32)];   // 128 KB adj bitmask

__device__ __forceinline__ uint32_t f2tf32(float f) {
    uint32_t r; asm("cvt.rna.tf32.f32 %0, %1;" : "=r"(r) : "f"(f)); return r;
}

__device__ __forceinline__ void mma_tf32(float c[4], const uint32_t a[4],
                                         uint32_t b0, uint32_t b1) {
    asm volatile(
        "mma.sync.aligned.m16n8k8.row.col.f32.tf32.tf32.f32 "
        "{%0,%1,%2,%3}, {%4,%5,%6,%7}, {%8,%9}, {%0,%1,%2,%3};"
        : "+f"(c[0]), "+f"(c[1]), "+f"(c[2]), "+f"(c[3])
        : "r"(a[0]), "r"(a[1]), "r"(a[2]), "r"(a[3]), "r"(b0), "r"(b1));
}

// ===== pre-pass: adj[1024][1024] int32 -> bitmask =====
__global__ void pack_mask_kernel(const int* __restrict__ adj) {
    int idx = blockIdx.x * blockDim.x + threadIdx.x;     // 0..32767
    const int4* src = (const int4*)(adj + (size_t)idx * 32);
    uint32_t m = 0;
    #pragma unroll
    for (int i = 0; i < 8; i++) {
        int4 v = src[i];
        m |= (v.x > 0 ? 1u : 0u) << (4 * i);
        m |= (v.y > 0 ? 1u : 0u) << (4 * i + 1);
        m |= (v.z > 0 ? 1u : 0u) << (4 * i + 2);
        m |= (v.w > 0 ? 1u : 0u) << (4 * i + 3);
    }
    g_maskbits[idx] = m;
}

// ===== main kernel =====
__global__ __launch_bounds__(NTHR, 3)
void attn_tf32_kernel2(const float* __restrict__ Qg, const float* __restrict__ Kg,
                       const float* __restrict__ Vg, float* __restrict__ Out) {
    extern __shared__ uint32_t smem[];
    uint32_t* Ksm = smem;                          // packed fragments
    uint32_t* Vsm = smem + (V_OFF / 4);            // padded rows

    const int tid  = threadIdx.x;
    const int w    = tid >> 5;
    const int lane = tid & 31;
    const int g    = lane >> 2;
    const int t4   = lane & 3;
    const int bh   = blockIdx.y;
    const int q0   = blockIdx.x * BM;
    const int rl0  = w * 16 + g;
    const int rl1  = rl0 + 8;
    const size_t headoff = (size_t)bh * NSEQ * DHEAD;

    // shuffle source lanes for P c-frag -> a-frag permutation (within quad)
    const int qbase = lane & ~3;
    const int src0  = qbase | (t4 >> 1);
    const int src2  = src0 + 2;
    const bool odd  = (t4 & 1) != 0;

    // ---- Q fragments, register resident ----
    uint32_t qa[16][4];
    {
        const float* Qp0 = Qg + headoff + (size_t)(q0 + rl0) * DHEAD;
        const float* Qp1 = Qg + headoff + (size_t)(q0 + rl1) * DHEAD;
        #pragma unroll
        for (int ks = 0; ks < 16; ks++) {
            int c = ks * 8 + t4;
            qa[ks][0] = f2tf32(Qp0[c]);
            qa[ks][1] = f2tf32(Qp1[c]);
            qa[ks][2] = f2tf32(Qp0[c + 4]);
            qa[ks][3] = f2tf32(Qp1[c + 4]);
        }
    }

    float oacc[16][4];
    #pragma unroll
    for (int nd = 0; nd < 16; nd++) {
        oacc[nd][0] = 0.f; oacc[nd][1] = 0.f; oacc[nd][2] = 0.f; oacc[nd][3] = 0.f;
    }
    float lsum0 = 0.f, lsum1 = 0.f;

    const uint32_t* mrow0 = g_maskbits + (size_t)(q0 + rl0) * 32;
    const uint32_t* mrow1 = g_maskbits + (size_t)(q0 + rl1) * 32;

    for (int kt = 0; kt < NSEQ / BN; kt++) {
        // mask words for this tile (L2-resident; issue early)
        uint32_t m00 = mrow0[kt * 2],     m01 = mrow0[kt * 2 + 1];
        uint32_t m10 = mrow1[kt * 2],     m11 = mrow1[kt * 2 + 1];

        __syncthreads();   // previous iteration's smem reads complete

        // ---- K tile -> packed B-fragment layout ----
        {
            const float* src = Kg + headoff + (size_t)kt * BN * DHEAD;
            #pragma unroll
            for (int i = 0; i < 16; i++) {
                int idx = tid + i * NTHR;           // float4 index 0..2047
                int row = idx >> 5;
                int c4i = idx & 31;                 // float4 col, c = 4*c4i
                float4 v = *(const float4*)(src + row * DHEAD + c4i * 4);
                int kp = c4i >> 2, s = c4i & 3, nb = row >> 3, gg = row & 7;
                uint32_t* f = Ksm + (nb * 8 + kp) * KF_WORDS + s;
                f[(gg * 4 + 0) * 4] = f2tf32(v.x);
                f[(gg * 4 + 1) * 4] = f2tf32(v.y);
                f[(gg * 4 + 2) * 4] = f2tf32(v.z);
                f[(gg * 4 + 3) * 4] = f2tf32(v.w);
            }
        }
        // ---- V tile -> padded row layout ----
        {
            const float* src = Vg + headoff + (size_t)kt * BN * DHEAD;
            #pragma unroll
            for (int i = 0; i < 16; i++) {
                int idx = tid + i * NTHR;
                int row = idx >> 5;
                int c4  = (idx & 31) << 2;
                float4 v = *(const float4*)(src + row * DHEAD + c4);
                uint4 u;
                u.x = f2tf32(v.x); u.y = f2tf32(v.y);
                u.z = f2tf32(v.z); u.w = f2tf32(v.w);
                *(uint4*)(Vsm + row * V_STRIDE + c4) = u;
            }
        }
        __syncthreads();

        // ---- process tile in two 32-col halves ----
        #pragma unroll
        for (int h = 0; h < 2; h++) {
            float sacc[4][4];
            #pragma unroll
            for (int nbl = 0; nbl < 4; nbl++) {
                sacc[nbl][0] = 0.f; sacc[nbl][1] = 0.f;
                sacc[nbl][2] = 0.f; sacc[nbl][3] = 0.f;
            }
            // S = Q K^T for cols [h*32, h*32+32)
            #pragma unroll
            for (int kp = 0; kp < 8; kp++) {
                #pragma unroll
                for (int nbl = 0; nbl < 4; nbl++) {
                    int nb = h * 4 + nbl;
                    uint4 kw = *(const uint4*)(Ksm + (nb * 8 + kp) * KF_WORDS + lane * 4);
                    mma_tf32(sacc[nbl], qa[2 * kp],     kw.x, kw.y);
                    mma_tf32(sacc[nbl], qa[2 * kp + 1], kw.z, kw.w);
                }
            }

            // mask + exp (no max subtraction: masked -> exactly 0, matching exp(-9e15))
            uint32_t mr0 = h ? m01 : m00;
            uint32_t mr1 = h ? m11 : m10;
            uint32_t pr[4][4];
            #pragma unroll
            for (int nbl = 0; nbl < 4; nbl++) {
                int bi = nbl * 8 + 2 * t4;
                float p0 = ((mr0 >> bi) & 1u)       ? __expf(sacc[nbl][0] * 0.125f) : 0.f;
                float p1 = ((mr0 >> (bi + 1)) & 1u) ? __expf(sacc[nbl][1] * 0.125f) : 0.f;
                float p2 = ((mr1 >> bi) & 1u)       ? __expf(sacc[nbl][2] * 0.125f) : 0.f;
                float p3 = ((mr1 >> (bi + 1)) & 1u) ? __expf(sacc[nbl][3] * 0.125f) : 0.f;
                lsum0 += p0 + p1;
                lsum1 += p2 + p3;
                pr[nbl][0] = f2tf32(p0); pr[nbl][1] = f2tf32(p1);
                pr[nbl][2] = f2tf32(p2); pr[nbl][3] = f2tf32(p3);
            }

            // O += P V for kv rows [kt*64 + h*32, +32)
            #pragma unroll
            for (int k2 = 0; k2 < 4; k2++) {
                int ks2 = h * 4 + k2;
                // c-frag -> a-frag permutation via quad shuffles
                uint32_t u0 = __shfl_sync(0xffffffffu, pr[k2][0], src0);
                uint32_t u1 = __shfl_sync(0xffffffffu, pr[k2][1], src0);
                uint32_t u2 = __shfl_sync(0xffffffffu, pr[k2][2], src0);
                uint32_t u3 = __shfl_sync(0xffffffffu, pr[k2][3], src0);
                uint32_t v0 = __shfl_sync(0xffffffffu, pr[k2][0], src2);
                uint32_t v1 = __shfl_sync(0xffffffffu, pr[k2][1], src2);
                uint32_t v2 = __shfl_sync(0xffffffffu, pr[k2][2], src2);
                uint32_t v3 = __shfl_sync(0xffffffffu, pr[k2][3], src2);
                uint32_t pa[4];
                pa[0] = odd ? u1 : u0;   // P[rl0][t4]
                pa[1] = odd ? u3 : u2;   // P[rl1][t4]
                pa[2] = odd ? v1 : v0;   // P[rl0][t4+4]
                pa[3] = odd ? v3 : v2;   // P[rl1][t4+4]

                const uint32_t* vb0 = Vsm + (ks2 * 8 + t4) * V_STRIDE + g;
                const uint32_t* vb1 = vb0 + 4 * V_STRIDE;
                #pragma unroll
                for (int nd = 0; nd < 16; nd++) {
                    mma_tf32(oacc[nd], pa, vb0[nd * 8], vb1[nd * 8]);
                }
            }
        }
    }

    // ---- epilogue: row-sum reduce within quad, normalize, store ----
    lsum0 += __shfl_xor_sync(0xffffffffu, lsum0, 1);
    lsum0 += __shfl_xor_sync(0xffffffffu, lsum0, 2);
    lsum1 += __shfl_xor_sync(0xffffffffu, lsum1, 1);
    lsum1 += __shfl_xor_sync(0xffffffffu, lsum1, 2);
    float inv0 = 1.0f / lsum0;
    float inv1 = 1.0f / lsum1;

    float* o0 = Out + headoff + (size_t)(q0 + rl0) * DHEAD;
    float* o1 = Out + headoff + (size_t)(q0 + rl1) * DHEAD;
    #pragma unroll
    for (int nd = 0; nd < 16; nd++) {
        int c = nd * 8 + 2 * t4;
        float2 a; a.x = oacc[nd][0] * inv0; a.y = oacc[nd][1] * inv0;
        *(float2*)(o0 + c) = a;
        float2 b; b.x = oacc[nd][2] * inv1; b.y = oacc[nd][3] * inv1;
        *(float2*)(o1 + c) = b;
    }
}

extern "C" void kernel_launch(void* const* d_in, const int* in_sizes, int n_in,
                              void* d_out, int out_size) {
    const float* Q   = (const float*)d_in[0];
    const float* K   = (const float*)d_in[1];
    const float* V   = (const float*)d_in[2];
    const int*   adj = (const int*)d_in[3];
    float* out = (float*)d_out;

    const int BH = in_sizes[0] / (NSEQ * DHEAD);   // 64

    pack_mask_kernel<<<NSEQ * (NSEQ / 32) / 256, 256>>>(adj);

    cudaFuncSetAttribute(attn_tf32_kernel2,
                         cudaFuncAttributeMaxDynamicSharedMemorySize, SMEM_TOTAL);

    dim3 grid(NSEQ / BM, BH);
    attn_tf32_kernel2<<<grid, NTHR, SMEM_TOTAL>>>(Q, K, V, out);
}

// round 4
// speedup vs baseline: 3.0723x; 2.8089x over previous
#include <cuda_runtime.h>
#include <cuda_fp16.h>
#include <cstdint>

#define NSEQ   1024
#define DHEAD  128
#define BM     64
#define BN     64
#define NTHR   128
#define BH_TOT 64
#define TILE_U4 1024          // uint4 per packed tile (16 KB)

// packed fp16 fragment-ready operands (16 MB each) + adj bitmask
__device__ uint4    g_Kp[BH_TOT * 16 * TILE_U4];
__device__ uint4    g_Vp[BH_TOT * 16 * TILE_U4];
__device__ uint32_t g_maskbits[NSEQ * (NSEQ / 32)];

__device__ __forceinline__ uint32_t h2pack(float a, float b) {
    __half2 h = __floats2half2_rn(a, b);
    return *reinterpret_cast<uint32_t*>(&h);
}

__device__ __forceinline__ void mma_f16(float c[4], const uint32_t a[4],
                                        uint32_t b0, uint32_t b1) {
    asm volatile(
        "mma.sync.aligned.m16n8k16.row.col.f32.f16.f16.f32 "
        "{%0,%1,%2,%3}, {%4,%5,%6,%7}, {%8,%9}, {%0,%1,%2,%3};"
        : "+f"(c[0]), "+f"(c[1]), "+f"(c[2]), "+f"(c[3])
        : "r"(a[0]), "r"(a[1]), "r"(a[2]), "r"(a[3]), "r"(b0), "r"(b1));
}

#define CPASYNC16(dst, src) \
    asm volatile("cp.async.cg.shared.global [%0], [%1], 16;" :: "r"(dst), "l"(src))
#define CPCOMMIT() asm volatile("cp.async.commit_group;")
#define CPWAIT0()  asm volatile("cp.async.wait_group 0;" ::: "memory")

// ===== prepass kernels =====
__global__ void pack_mask_kernel(const int* __restrict__ adj) {
    int idx = blockIdx.x * blockDim.x + threadIdx.x;     // 0..32767
    const int4* src = (const int4*)(adj + (size_t)idx * 32);
    uint32_t m = 0;
    #pragma unroll
    for (int i = 0; i < 8; i++) {
        int4 v = src[i];
        m |= (v.x > 0 ? 1u : 0u) << (4 * i);
        m |= (v.y > 0 ? 1u : 0u) << (4 * i + 1);
        m |= (v.z > 0 ? 1u : 0u) << (4 * i + 2);
        m |= (v.w > 0 ? 1u : 0u) << (4 * i + 3);
    }
    g_maskbits[idx] = m;
}

// K fragment pack: out uint4 index = ((bh*16+kt)*8+nb)*4+kpp, lane
// b-frags for S = Q K^T : b0={K[n][k],K[n][k+1]}, b1=+8, (two k-steps per uint4)
__global__ void pack_k_kernel(const float* __restrict__ K) {
    int t = blockIdx.x * blockDim.x + threadIdx.x;       // 0..1048575
    int lane = t & 31, kpp = (t >> 5) & 3, nb = (t >> 7) & 7;
    int kt = (t >> 10) & 15, bh = t >> 14;
    int g = lane >> 2, t4 = lane & 3;
    const float* src = K + ((size_t)bh * NSEQ + kt * 64 + nb * 8 + g) * DHEAD
                         + 32 * kpp + 2 * t4;
    uint4 o;
    o.x = h2pack(src[0],  src[1]);
    o.y = h2pack(src[8],  src[9]);
    o.z = h2pack(src[16], src[17]);
    o.w = h2pack(src[24], src[25]);
    g_Kp[t] = o;
}

// V fragment pack: b-frags for O = P V : b0={V[ra][c],V[ra+1][c]}, b1={V[ra+8][c],V[ra+9][c]}
__global__ void pack_v_kernel(const float* __restrict__ V) {
    int t = blockIdx.x * blockDim.x + threadIdx.x;
    int lane = t & 31, nd2 = (t >> 5) & 7, ks2 = (t >> 8) & 3;
    int kt = (t >> 10) & 15, bh = t >> 14;
    int g = lane >> 2, t4 = lane & 3;
    int ra = kt * 64 + 16 * ks2 + 2 * t4;
    int c0 = 16 * nd2 + g;
    const float* src = V + ((size_t)bh * NSEQ + ra) * DHEAD;
    uint4 o;
    o.x = h2pack(src[c0],              src[DHEAD + c0]);
    o.y = h2pack(src[8 * DHEAD + c0],  src[9 * DHEAD + c0]);
    o.z = h2pack(src[c0 + 8],          src[DHEAD + c0 + 8]);
    o.w = h2pack(src[8 * DHEAD + c0 + 8], src[9 * DHEAD + c0 + 8]);
    g_Vp[t] = o;
}

// ===== main kernel =====
__global__ __launch_bounds__(NTHR, 3)
void attn_f16_kernel(const float* __restrict__ Qg, float* __restrict__ Out) {
    __shared__ uint4 smem[2 * TILE_U4];                  // K tile | V tile (32 KB)
    uint4* sK = smem;
    uint4* sV = smem + TILE_U4;
    const uint32_t sbase = (uint32_t)__cvta_generic_to_shared(smem);

    const int tid  = threadIdx.x;
    const int w    = tid >> 5;
    const int lane = tid & 31;
    const int g    = lane >> 2;
    const int t4   = lane & 3;
    const int bh   = blockIdx.y;
    const int q0   = blockIdx.x * BM;
    const int rl0  = w * 16 + g;
    const int rl1  = rl0 + 8;
    const size_t headoff = (size_t)bh * NSEQ * DHEAD;

    // ---- Q a-fragments (fp16, register resident) ----
    uint32_t qa[8][4];
    {
        const float* Qp0 = Qg + headoff + (size_t)(q0 + rl0) * DHEAD;
        const float* Qp1 = Qg + headoff + (size_t)(q0 + rl1) * DHEAD;
        #pragma unroll
        for (int ks = 0; ks < 8; ks++) {
            int c = ks * 16 + 2 * t4;
            qa[ks][0] = h2pack(Qp0[c],     Qp0[c + 1]);
            qa[ks][1] = h2pack(Qp1[c],     Qp1[c + 1]);
            qa[ks][2] = h2pack(Qp0[c + 8], Qp0[c + 9]);
            qa[ks][3] = h2pack(Qp1[c + 8], Qp1[c + 9]);
        }
    }

    float oacc[16][4];
    #pragma unroll
    for (int nd = 0; nd < 16; nd++) {
        oacc[nd][0] = 0.f; oacc[nd][1] = 0.f; oacc[nd][2] = 0.f; oacc[nd][3] = 0.f;
    }
    float lsum0 = 0.f, lsum1 = 0.f;

    const uint32_t* mrow0 = g_maskbits + (size_t)(q0 + rl0) * 32;
    const uint32_t* mrow1 = g_maskbits + (size_t)(q0 + rl1) * 32;

    for (int kt = 0; kt < NSEQ / BN; kt++) {
        uint32_t m00 = mrow0[kt * 2], m01 = mrow0[kt * 2 + 1];
        uint32_t m10 = mrow1[kt * 2], m11 = mrow1[kt * 2 + 1];

        __syncthreads();   // previous tile's smem reads done

        // ---- cp.async raw copy of pre-packed tiles ----
        {
            const uint4* gK = g_Kp + (size_t)(bh * 16 + kt) * TILE_U4;
            const uint4* gV = g_Vp + (size_t)(bh * 16 + kt) * TILE_U4;
            #pragma unroll
            for (int i = 0; i < 8; i++) {
                int idx = tid + i * NTHR;
                CPASYNC16(sbase + idx * 16,           gK + idx);
                CPASYNC16(sbase + 16384 + idx * 16,   gV + idx);
            }
            CPCOMMIT();
            CPWAIT0();
        }
        __syncthreads();

        // ---- two 32-col halves: S -> exp -> PV ----
        #pragma unroll
        for (int h = 0; h < 2; h++) {
            float sacc[4][4];
            #pragma unroll
            for (int nbl = 0; nbl < 4; nbl++) {
                sacc[nbl][0] = 0.f; sacc[nbl][1] = 0.f;
                sacc[nbl][2] = 0.f; sacc[nbl][3] = 0.f;
            }
            #pragma unroll
            for (int kpp = 0; kpp < 4; kpp++) {
                #pragma unroll
                for (int nbl = 0; nbl < 4; nbl++) {
                    int nb = h * 4 + nbl;
                    uint4 kw = sK[(nb * 4 + kpp) * 32 + lane];
                    mma_f16(sacc[nbl], qa[2 * kpp],     kw.x, kw.y);
                    mma_f16(sacc[nbl], qa[2 * kpp + 1], kw.z, kw.w);
                }
            }

            uint32_t mr0 = h ? m01 : m00;
            uint32_t mr1 = h ? m11 : m10;
            uint32_t pa2[2][4];          // a-frags for the 2 PV k-steps of this half
            #pragma unroll
            for (int nbl = 0; nbl < 4; nbl++) {
                int bi = nbl * 8 + 2 * t4;
                float p0 = ((mr0 >> bi) & 1u)       ? __expf(sacc[nbl][0] * 0.125f) : 0.f;
                float p1 = ((mr0 >> (bi + 1)) & 1u) ? __expf(sacc[nbl][1] * 0.125f) : 0.f;
                float p2 = ((mr1 >> bi) & 1u)       ? __expf(sacc[nbl][2] * 0.125f) : 0.f;
                float p3 = ((mr1 >> (bi + 1)) & 1u) ? __expf(sacc[nbl][3] * 0.125f) : 0.f;
                lsum0 += p0 + p1;
                lsum1 += p2 + p3;
                // fp16 S c-frag == PV a-frag rows (half2-packed): no shuffles needed
                int j = nbl >> 1;
                if ((nbl & 1) == 0) {
                    pa2[j][0] = h2pack(p0, p1);
                    pa2[j][1] = h2pack(p2, p3);
                } else {
                    pa2[j][2] = h2pack(p0, p1);
                    pa2[j][3] = h2pack(p2, p3);
                }
            }

            #pragma unroll
            for (int j = 0; j < 2; j++) {
                int ks2 = 2 * h + j;
                #pragma unroll
                for (int nd2 = 0; nd2 < 8; nd2++) {
                    uint4 vw = sV[(ks2 * 8 + nd2) * 32 + lane];
                    mma_f16(oacc[2 * nd2],     pa2[j], vw.x, vw.y);
                    mma_f16(oacc[2 * nd2 + 1], pa2[j], vw.z, vw.w);
                }
            }
        }
    }

    // ---- epilogue ----
    lsum0 += __shfl_xor_sync(0xffffffffu, lsum0, 1);
    lsum0 += __shfl_xor_sync(0xffffffffu, lsum0, 2);
    lsum1 += __shfl_xor_sync(0xffffffffu, lsum1, 1);
    lsum1 += __shfl_xor_sync(0xffffffffu, lsum1, 2);
    float inv0 = 1.0f / lsum0;
    float inv1 = 1.0f / lsum1;

    float* o0 = Out + headoff + (size_t)(q0 + rl0) * DHEAD;
    float* o1 = Out + headoff + (size_t)(q0 + rl1) * DHEAD;
    #pragma unroll
    for (int nd = 0; nd < 16; nd++) {
        int c = nd * 8 + 2 * t4;
        float2 a; a.x = oacc[nd][0] * inv0; a.y = oacc[nd][1] * inv0;
        *(float2*)(o0 + c) = a;
        float2 b; b.x = oacc[nd][2] * inv1; b.y = oacc[nd][3] * inv1;
        *(float2*)(o1 + c) = b;
    }
}

extern "C" void kernel_launch(void* const* d_in, const int* in_sizes, int n_in,
                              void* d_out, int out_size) {
    const float* Q   = (const float*)d_in[0];
    const float* K   = (const float*)d_in[1];
    const float* V   = (const float*)d_in[2];
    const int*   adj = (const int*)d_in[3];
    float* out = (float*)d_out;

    const int BH = in_sizes[0] / (NSEQ * DHEAD);     // 64

    pack_mask_kernel<<<NSEQ * (NSEQ / 32) / 256, 256>>>(adj);
    pack_k_kernel<<<(BH * 16 * TILE_U4) / 256, 256>>>(K);
    pack_v_kernel<<<(BH * 16 * TILE_U4) / 256, 256>>>(V);

    dim3 grid(NSEQ / BM, BH);
    attn_f16_kernel<<<grid, NTHR>>>(Q, out);
}

// round 8
// speedup vs baseline: 3.2578x; 1.0604x over previous
#include <cuda_runtime.h>
#include <cuda_fp16.h>
#include <cstdint>

#define NSEQ   1024
#define DHEAD  128
#define BM     64
#define BN     64
#define NTHR   128
#define BH_TOT 64
#define TILE_U4 1024          // uint4 per packed tile (16 KB)
#define SMEM_BYTES (4 * TILE_U4 * 16)   // 2 stages x (K|V) = 64 KB

// packed fp16 fragment-ready operands (16 MB each) + adj bitmask
__device__ uint4    g_Kp[BH_TOT * 16 * TILE_U4];
__device__ uint4    g_Vp[BH_TOT * 16 * TILE_U4];
__device__ uint32_t g_maskbits[NSEQ * (NSEQ / 32)];

__device__ __forceinline__ uint32_t h2pack(float a, float b) {
    __half2 h = __floats2half2_rn(a, b);
    return *reinterpret_cast<uint32_t*>(&h);
}

__device__ __forceinline__ void mma_f16(float c[4], const uint32_t a[4],
                                        uint32_t b0, uint32_t b1) {
    asm volatile(
        "mma.sync.aligned.m16n8k16.row.col.f32.f16.f16.f32 "
        "{%0,%1,%2,%3}, {%4,%5,%6,%7}, {%8,%9}, {%0,%1,%2,%3};"
        : "+f"(c[0]), "+f"(c[1]), "+f"(c[2]), "+f"(c[3])
        : "r"(a[0]), "r"(a[1]), "r"(a[2]), "r"(a[3]), "r"(b0), "r"(b1));
}

#define CPASYNC16(dst, src) \
    asm volatile("cp.async.cg.shared.global [%0], [%1], 16;" :: "r"(dst), "l"(src))
#define CPCOMMIT() asm volatile("cp.async.commit_group;")
#define CPWAIT1()  asm volatile("cp.async.wait_group 1;" ::: "memory")

// ===== prepass kernels =====
__global__ void pack_mask_kernel(const int* __restrict__ adj) {
    int idx = blockIdx.x * blockDim.x + threadIdx.x;     // 0..32767
    const int4* src = (const int4*)(adj + (size_t)idx * 32);
    uint32_t m = 0;
    #pragma unroll
    for (int i = 0; i < 8; i++) {
        int4 v = src[i];
        m |= (v.x > 0 ? 1u : 0u) << (4 * i);
        m |= (v.y > 0 ? 1u : 0u) << (4 * i + 1);
        m |= (v.z > 0 ? 1u : 0u) << (4 * i + 2);
        m |= (v.w > 0 ? 1u : 0u) << (4 * i + 3);
    }
    g_maskbits[idx] = m;
}

// Fused K+V fragment pack. blockIdx.y==0 -> K, ==1 -> V.
__global__ void pack_kv_kernel(const float* __restrict__ K, const float* __restrict__ V) {
    int t = blockIdx.x * blockDim.x + threadIdx.x;       // 0..1048575
    int lane = t & 31;
    int g = lane >> 2, t4 = lane & 3;
    int kt = (t >> 10) & 15, bh = t >> 14;
    if (blockIdx.y == 0) {
        // K b-frags for S = Q K^T
        int kpp = (t >> 5) & 3, nb = (t >> 7) & 7;
        const float* src = K + ((size_t)bh * NSEQ + kt * 64 + nb * 8 + g) * DHEAD
                             + 32 * kpp + 2 * t4;
        uint4 o;
        o.x = h2pack(src[0],  src[1]);
        o.y = h2pack(src[8],  src[9]);
        o.z = h2pack(src[16], src[17]);
        o.w = h2pack(src[24], src[25]);
        g_Kp[t] = o;
    } else {
        // V b-frags for O = P V
        int nd2 = (t >> 5) & 7, ks2 = (t >> 8) & 3;
        int ra = kt * 64 + 16 * ks2 + 2 * t4;
        int c0 = 16 * nd2 + g;
        const float* src = V + ((size_t)bh * NSEQ + ra) * DHEAD;
        uint4 o;
        o.x = h2pack(src[c0],                 src[DHEAD + c0]);
        o.y = h2pack(src[8 * DHEAD + c0],     src[9 * DHEAD + c0]);
        o.z = h2pack(src[c0 + 8],             src[DHEAD + c0 + 8]);
        o.w = h2pack(src[8 * DHEAD + c0 + 8], src[9 * DHEAD + c0 + 8]);
        g_Vp[t] = o;
    }
}

// ===== main kernel =====
__global__ __launch_bounds__(NTHR, 3)
void attn_f16_kernel(const float* __restrict__ Qg, float* __restrict__ Out) {
    extern __shared__ uint4 smem[];                      // [2][2048]: stage -> K(1024)|V(1024)
    const uint32_t sbase = (uint32_t)__cvta_generic_to_shared(smem);

    const int tid  = threadIdx.x;
    const int w    = tid >> 5;
    const int lane = tid & 31;
    const int g    = lane >> 2;
    const int t4   = lane & 3;
    const int bh   = blockIdx.y;
    const int q0   = blockIdx.x * BM;
    const int rl0  = w * 16 + g;
    const int rl1  = rl0 + 8;
    const size_t headoff = (size_t)bh * NSEQ * DHEAD;

    const uint4* gK = g_Kp + (size_t)bh * 16 * TILE_U4;
    const uint4* gV = g_Vp + (size_t)bh * 16 * TILE_U4;

    // ---- prefetch tile 0 into stage 0 ----
    #pragma unroll
    for (int i = 0; i < 8; i++) {
        int idx = tid + i * NTHR;
        CPASYNC16(sbase + idx * 16,         gK + idx);
        CPASYNC16(sbase + 16384 + idx * 16, gV + idx);
    }
    CPCOMMIT();

    // ---- Q a-fragments (fp16, register resident) ----
    uint32_t qa[8][4];
    {
        const float* Qp0 = Qg + headoff + (size_t)(q0 + rl0) * DHEAD;
        const float* Qp1 = Qg + headoff + (size_t)(q0 + rl1) * DHEAD;
        #pragma unroll
        for (int ks = 0; ks < 8; ks++) {
            int c = ks * 16 + 2 * t4;
            qa[ks][0] = h2pack(Qp0[c],     Qp0[c + 1]);
            qa[ks][1] = h2pack(Qp1[c],     Qp1[c + 1]);
            qa[ks][2] = h2pack(Qp0[c + 8], Qp0[c + 9]);
            qa[ks][3] = h2pack(Qp1[c + 8], Qp1[c + 9]);
        }
    }

    float oacc[16][4];
    #pragma unroll
    for (int nd = 0; nd < 16; nd++) {
        oacc[nd][0] = 0.f; oacc[nd][1] = 0.f; oacc[nd][2] = 0.f; oacc[nd][3] = 0.f;
    }
    float lsum0 = 0.f, lsum1 = 0.f;

    const uint32_t* mrow0 = g_maskbits + (size_t)(q0 + rl0) * 32;
    const uint32_t* mrow1 = g_maskbits + (size_t)(q0 + rl1) * 32;

    for (int kt = 0; kt < NSEQ / BN; kt++) {
        const int cur = kt & 1;

        // masks for this tile (L2 hits; issued early, consumed after S-mma)
        uint32_t m00 = mrow0[kt * 2], m01 = mrow0[kt * 2 + 1];
        uint32_t m10 = mrow1[kt * 2], m11 = mrow1[kt * 2 + 1];

        __syncthreads();   // all warps finished computing on the spare stage

        // prefetch next tile into the spare stage
        if (kt + 1 < NSEQ / BN) {
            const uint4* nK = gK + (size_t)(kt + 1) * TILE_U4;
            const uint4* nV = gV + (size_t)(kt + 1) * TILE_U4;
            uint32_t dst = sbase + (cur ^ 1) * 32768;
            #pragma unroll
            for (int i = 0; i < 8; i++) {
                int idx = tid + i * NTHR;
                CPASYNC16(dst + idx * 16,         nK + idx);
                CPASYNC16(dst + 16384 + idx * 16, nV + idx);
            }
        }
        CPCOMMIT();
        CPWAIT1();         // current tile has landed (1 group may stay in flight)
        __syncthreads();

        const uint4* sK = smem + cur * 2048;
        const uint4* sV = sK + 1024;

        // ---- two 32-col halves: S -> exp -> PV ----
        #pragma unroll
        for (int h = 0; h < 2; h++) {
            float sacc[4][4];
            #pragma unroll
            for (int nbl = 0; nbl < 4; nbl++) {
                sacc[nbl][0] = 0.f; sacc[nbl][1] = 0.f;
                sacc[nbl][2] = 0.f; sacc[nbl][3] = 0.f;
            }
            #pragma unroll
            for (int kpp = 0; kpp < 4; kpp++) {
                #pragma unroll
                for (int nbl = 0; nbl < 4; nbl++) {
                    int nb = h * 4 + nbl;
                    uint4 kw = sK[(nb * 4 + kpp) * 32 + lane];
                    mma_f16(sacc[nbl], qa[2 * kpp],     kw.x, kw.y);
                    mma_f16(sacc[nbl], qa[2 * kpp + 1], kw.z, kw.w);
                }
            }

            uint32_t mr0 = h ? m01 : m00;
            uint32_t mr1 = h ? m11 : m10;
            uint32_t pa2[2][4];          // a-frags for the 2 PV k-steps of this half
            #pragma unroll
            for (int nbl = 0; nbl < 4; nbl++) {
                int bi = nbl * 8 + 2 * t4;
                float p0 = ((mr0 >> bi) & 1u)       ? __expf(sacc[nbl][0] * 0.125f) : 0.f;
                float p1 = ((mr0 >> (bi + 1)) & 1u) ? __expf(sacc[nbl][1] * 0.125f) : 0.f;
                float p2 = ((mr1 >> bi) & 1u)       ? __expf(sacc[nbl][2] * 0.125f) : 0.f;
                float p3 = ((mr1 >> (bi + 1)) & 1u) ? __expf(sacc[nbl][3] * 0.125f) : 0.f;
                lsum0 += p0 + p1;
                lsum1 += p2 + p3;
                // fp16 S c-frag == PV a-frag rows (half2-packed): no shuffles needed
                int j = nbl >> 1;
                if ((nbl & 1) == 0) {
                    pa2[j][0] = h2pack(p0, p1);
                    pa2[j][1] = h2pack(p2, p3);
                } else {
                    pa2[j][2] = h2pack(p0, p1);
                    pa2[j][3] = h2pack(p2, p3);
                }
            }

            #pragma unroll
            for (int j = 0; j < 2; j++) {
                int ks2 = 2 * h + j;
                #pragma unroll
                for (int nd2 = 0; nd2 < 8; nd2++) {
                    uint4 vw = sV[(ks2 * 8 + nd2) * 32 + lane];
                    mma_f16(oacc[2 * nd2],     pa2[j], vw.x, vw.y);
                    mma_f16(oacc[2 * nd2 + 1], pa2[j], vw.z, vw.w);
                }
            }
        }
    }

    // ---- epilogue ----
    lsum0 += __shfl_xor_sync(0xffffffffu, lsum0, 1);
    lsum0 += __shfl_xor_sync(0xffffffffu, lsum0, 2);
    lsum1 += __shfl_xor_sync(0xffffffffu, lsum1, 1);
    lsum1 += __shfl_xor_sync(0xffffffffu, lsum1, 2);
    float inv0 = 1.0f / lsum0;
    float inv1 = 1.0f / lsum1;

    float* o0 = Out + headoff + (size_t)(q0 + rl0) * DHEAD;
    float* o1 = Out + headoff + (size_t)(q0 + rl1) * DHEAD;
    #pragma unroll
    for (int nd = 0; nd < 16; nd++) {
        int c = nd * 8 + 2 * t4;
        float2 a; a.x = oacc[nd][0] * inv0; a.y = oacc[nd][1] * inv0;
        *(float2*)(o0 + c) = a;
        float2 b; b.x = oacc[nd][2] * inv1; b.y = oacc[nd][3] * inv1;
        *(float2*)(o1 + c) = b;
    }
}

extern "C" void kernel_launch(void* const* d_in, const int* in_sizes, int n_in,
                              void* d_out, int out_size) {
    const float* Q   = (const float*)d_in[0];
    const float* K   = (const float*)d_in[1];
    const float* V   = (const float*)d_in[2];
    const int*   adj = (const int*)d_in[3];
    float* out = (float*)d_out;

    const int BH = in_sizes[0] / (NSEQ * DHEAD);     // 64

    pack_mask_kernel<<<NSEQ * (NSEQ / 32) / 256, 256>>>(adj);
    {
        dim3 pg((BH * 16 * TILE_U4) / 256, 2);
        pack_kv_kernel<<<pg, 256>>>(K, V);
    }

    cudaFuncSetAttribute(attn_f16_kernel,
                         cudaFuncAttributeMaxDynamicSharedMemorySize, SMEM_BYTES);

    dim3 grid(NSEQ / BM, BH);
    attn_f16_kernel<<<grid, NTHR, SMEM_BYTES>>>(Q, out);
}